// round 16
// baseline (speedup 1.0000x reference)
#include <cuda_runtime.h>

// CCSDS-123 lossless predictor, [Z=224, Y=512, X=512].
// 4 rows per 512-thread block, flat one-barrier structure, streaming stores.
// Prev-band values go straight to registers (no smem round-trip — they need
// no neighbor shift), issued before the barrier so latency hides under it.
// reconstructed == sample_representatives == clip(img) == img exactly.

#define ZB 224
#define YB 512
#define XB 512

static constexpr size_t PLANE = (size_t)ZB * YB * XB;   // 58,720,256

__global__ __launch_bounds__(512, 4) void ccsds123_kernel(
    const float* __restrict__ img, float* __restrict__ out)
{
    const int b   = blockIdx.x;          // 224 * 128 blocks
    const int z   = b >> 7;              // / 128
    const int y0  = (b & 127) << 2;      // row quad
    const int tid = threadIdx.x;

    __shared__ float SC[4 * XB];   // center rows y0..y0+3
    __shared__ float SN[XB];       // north row  y0-1

    const int q  = tid >> 7;                 // which of the four rows
    const int t  = tid & 127;
    const int x0 = t * 4;
    const int y  = y0 + q;

    const float* base  = img + ((size_t)z * YB + y0) * XB;

    // Prev-band co-located values: straight to registers, issued first so the
    // latency overlaps the staging loads + barrier. Last reader of these lines
    // in block-issue order -> evict-first (.cs).
    float4 pv = make_float4(0.f, 0.f, 0.f, 0.f);
    if (z > 0) {
        const float* p = base - (size_t)YB * XB + (size_t)q * XB + x0;
        pv.x = __ldcs(p + 0);
        pv.y = __ldcs(p + 1);
        pv.z = __ldcs(p + 2);
        pv.w = __ldcs(p + 3);
    }

    // Stage center rows (512 float4s = 4 rows) and the north row.
    ((float4*)SC)[tid] = ((const float4*)base)[tid];
    if (tid < 128)
        ((float4*)SN)[tid] = (y0 > 0) ? ((const float4*)(base - XB))[tid]
                                      : make_float4(0.f, 0.f, 0.f, 0.f);
    __syncthreads();

    const float* sc = SC + q * XB;                     // center s(z, y, :)
    const float* sn = q ? (SC + (q - 1) * XB) : SN;    // north  s(z, y-1, :)
    const float  pbv[4] = {pv.x, pv.y, pv.z, pv.w};    // prev   s(z-1, y, :)

    float pr[4], rs[4], mp[4], cv[4];

#pragma unroll
    for (int i = 0; i < 4; ++i) {
        const int x = x0 + i;
        const float Cv  = sc[x];
        const float Wv  = (x > 0)      ? sc[x - 1] : 0.f;
        const float Nv  = sn[x];
        const float NWv = (x > 0)      ? sn[x - 1] : 0.f;
        const float NEv = (x < XB - 1) ? sn[x + 1] : 0.f;

        // neighbor-oriented local sum with edge cases
        float sigma;
        if (y == 0)           sigma = (x == 0) ? 0.f : 4.f * Wv;   // top row
        else if (x == 0)      sigma = 2.f * (Nv + NEv);            // left col
        else if (x == XB - 1) sigma = Wv + NWv + 2.f * Nv;         // right col
        else                  sigma = Wv + NWv + Nv + NEv;         // interior

        const float spred = sigma * 0.25f;
        const float pb    = pbv[i];

        float p = (z == 0) ? spred : 0.5f * (spred + pb);
        if (y == 0 && x == 0) p = (z == 0) ? 0.f : pb;             // origin

        const float r  = Cv - p;                   // residual (== quantized)
        const float qv = rintf(r);                 // half-to-even, matches jnp.round
        const float m  = (qv >= 0.f) ? (2.f * qv) : (-2.f * qv - 1.f); // zigzag

        pr[i] = p; rs[i] = r; mp[i] = m;
        cv[i] = Cv;   // reconstructed == sample_repr == clip(p + r) == Cv exactly
    }

    const size_t off = ((size_t)z * YB + y) * XB + (size_t)x0;
    const float4 v_p = make_float4(pr[0], pr[1], pr[2], pr[3]);
    const float4 v_r = make_float4(rs[0], rs[1], rs[2], rs[3]);
    const float4 v_m = make_float4(mp[0], mp[1], mp[2], mp[3]);
    const float4 v_c = make_float4(cv[0], cv[1], cv[2], cv[3]);

    __stcs((float4*)(out + off),             v_p);  // predictions
    __stcs((float4*)(out + off + PLANE),     v_r);  // residuals
    __stcs((float4*)(out + off + 2 * PLANE), v_r);  // quantized residuals
    __stcs((float4*)(out + off + 3 * PLANE), v_m);  // mapped indices
    __stcs((float4*)(out + off + 4 * PLANE), v_c);  // sample representatives
    __stcs((float4*)(out + off + 5 * PLANE), v_c);  // reconstructed
}

extern "C" void kernel_launch(void* const* d_in, const int* in_sizes, int n_in,
                              void* d_out, int out_size)
{
    const float* img = (const float*)d_in[0];
    float* out = (float*)d_out;
    ccsds123_kernel<<<ZB * (YB / 4), 512>>>(img, out);
}